// round 1
// baseline (speedup 1.0000x reference)
#include <cuda_runtime.h>
#include <math.h>

#define B 64
#define C 256

// ---------------- scratch (static device globals; no allocation) ----------------
__device__ float g_lf[B*C*7*7];        // conv_target(large)  (64,256,7,7)
__device__ float g_mf[B*C*5*5];        // conv_target(medium) (64,256,5,5)
__device__ float g_sf[B*C*3*3];        // conv_target(small)  (64,256,3,3)
__device__ float g_s [B*C*29*29];      // conv_search(search) (64,256,29,29)
__device__ float g_lc[B*C*27*27];      // corr large  (64,256,27,27)
__device__ float g_mc[B*C*25*25];      // corr medium (64,256,25,25)
__device__ float g_sc[B*C*27*27];      // corr small  (64,256,27,27)
__device__ float g_scale_t[C], g_bias_t[C];
__device__ float g_scale_s[C], g_bias_s[C];
__device__ float g_scale_1[C], g_bias_1[C];

// ---------------- BN folding: y = scale*conv + bias ----------------
__global__ void prep_kernel(const float* bt,const float* gt,const float* bet,const float* mt,const float* vt,
                            const float* bs,const float* gs,const float* bes,const float* ms,const float* vs,
                            const float* b1,const float* g1,const float* be1,const float* m1,const float* v1){
    int c = threadIdx.x;
    {
        float inv = gt[c] * rsqrtf(vt[c] + 1e-5f);
        g_scale_t[c] = inv;
        g_bias_t[c]  = bt[c]*inv + bet[c] - mt[c]*inv;
    }
    {
        float inv = gs[c] * rsqrtf(vs[c] + 1e-5f);
        g_scale_s[c] = inv;
        g_bias_s[c]  = bs[c]*inv + bes[c] - ms[c]*inv;
    }
    {
        float inv = g1[c] * rsqrtf(v1[c] + 1e-5f);
        g_scale_1[c] = inv;
        g_bias_1[c]  = b1[c]*inv + be1[c] - m1[c]*inv;
    }
}

// ---------------- template conv 3x3 valid + BN + ReLU (small spatial) ----------------
// block: (batch b, 32-oc group). threads: 256 = 32 oc x 8 pixel-slots.
template<int H>
__global__ void __launch_bounds__(256) conv_tmpl(const float* __restrict__ in,
                                                 const float* __restrict__ w,
                                                 float* __restrict__ out){
    constexpr int OH = H - 2;
    constexpr int NP = OH * OH;
    constexpr int NA = (NP + 7) / 8;
    __shared__ float s_in[16 * H * H];
    __shared__ float s_w[32 * 16 * 9];
    int tid = threadIdx.x;
    int ps  = tid & 7;
    int ocl = tid >> 3;                     // 0..31
    int b = blockIdx.x;
    int ocbase = blockIdx.y * 32;

    int  off[NA];
    bool valid[NA];
#pragma unroll
    for (int a = 0; a < NA; a++){
        int p = ps + a * 8;
        valid[a] = (p < NP);
        int pp = valid[a] ? p : 0;
        off[a] = (pp / OH) * H + (pp % OH);
    }
    float acc[NA];
#pragma unroll
    for (int a = 0; a < NA; a++) acc[a] = 0.f;

    const float* inb = in + (size_t)b * C * H * H;
    for (int ic0 = 0; ic0 < C; ic0 += 16){
        __syncthreads();
#pragma unroll 1
        for (int idx = tid; idx < 16 * H * H; idx += 256)
            s_in[idx] = inb[ic0 * H * H + idx];
#pragma unroll 1
        for (int idx = tid; idx < 32 * 16 * 9; idx += 256){
            int k  = idx % 9;
            int ic = (idx / 9) & 15;
            int oc = idx / (9 * 16);
            s_w[idx] = w[((ocbase + oc) * C + ic0 + ic) * 9 + k];
        }
        __syncthreads();
#pragma unroll
        for (int ic = 0; ic < 16; ic++){
            float wr[9];
#pragma unroll
            for (int k = 0; k < 9; k++) wr[k] = s_w[(ocl * 16 + ic) * 9 + k];
            const float* ip = s_in + ic * H * H;
#pragma unroll
            for (int a = 0; a < NA; a++){
                const float* q = ip + off[a];
                acc[a] += q[0]*wr[0] + q[1]*wr[1] + q[2]*wr[2]
                        + q[H]*wr[3] + q[H+1]*wr[4] + q[H+2]*wr[5]
                        + q[2*H]*wr[6] + q[2*H+1]*wr[7] + q[2*H+2]*wr[8];
            }
        }
    }
    float sc = g_scale_t[ocbase + ocl], bi = g_bias_t[ocbase + ocl];
    float* op = out + ((size_t)b * C + ocbase + ocl) * NP;
#pragma unroll
    for (int a = 0; a < NA; a++){
        if (valid[a]){
            float v = fmaf(sc, acc[a], bi);
            op[ps + a * 8] = v > 0.f ? v : 0.f;
        }
    }
}

// ---------------- search conv 3x3 valid + BN + ReLU (31x31 -> 29x29) ----------------
// block: (b, 16-oc group, 16-row tile). 256 thr = 4 oc-quads x 16 rows x 4 col-groups.
// per-thread register tile: 4 oc x 8 consecutive cols. FMA:LDS ~ 4.4:1, conflict-free.
__global__ void __launch_bounds__(256) conv_search(const float* __restrict__ in,
                                                   const float* __restrict__ w){
    __shared__ float s_in[4 * 18 * 33];   // 4 ic, 18 rows, stride-33 pad
    __shared__ float s_w[16 * 4 * 9];
    int tid = threadIdx.x;
    int c  = tid & 3;            // col group (8 cols each)
    int r  = (tid >> 2) & 15;    // row within tile
    int cz = tid >> 6;           // oc quad (0..3), uniform per warp
    int b = blockIdx.x;
    int ocbase = blockIdx.y * 16;
    int row0 = blockIdx.z * 16;

    float acc[4][8];
#pragma unroll
    for (int i = 0; i < 4; i++)
#pragma unroll
        for (int j = 0; j < 8; j++) acc[i][j] = 0.f;

    const float* inb = in + (size_t)b * C * 31 * 31;
    for (int ic0 = 0; ic0 < C; ic0 += 4){
        __syncthreads();
#pragma unroll 1
        for (int idx = tid; idx < 4 * 18 * 32; idx += 256){
            int col = idx & 31;
            int row = (idx >> 5) % 18;
            int ic  = idx / (18 * 32);
            int grow = row0 + row;
            float v = 0.f;
            if (col < 31 && grow < 31) v = inb[((ic0 + ic) * 31 + grow) * 31 + col];
            s_in[ic * (18 * 33) + row * 33 + col] = v;
        }
#pragma unroll 1
        for (int idx = tid; idx < 16 * 4 * 9; idx += 256){
            int k  = idx % 9;
            int ic = (idx / 9) & 3;
            int oc = idx / 36;
            s_w[idx] = w[((ocbase + oc) * C + ic0 + ic) * 9 + k];
        }
        __syncthreads();
#pragma unroll
        for (int ic = 0; ic < 4; ic++){
            const float* sp = s_in + ic * (18 * 33) + r * 33 + c * 8;
#pragma unroll
            for (int kh = 0; kh < 3; kh++){
                float rv[10];
#pragma unroll
                for (int j = 0; j < 10; j++) rv[j] = sp[kh * 33 + j];
#pragma unroll
                for (int i = 0; i < 4; i++){
                    const float* wp = s_w + ((cz * 4 + i) * 4 + ic) * 9 + kh * 3;
                    float w0 = wp[0], w1 = wp[1], w2 = wp[2];
#pragma unroll
                    for (int j = 0; j < 8; j++)
                        acc[i][j] += rv[j]*w0 + rv[j+1]*w1 + rv[j+2]*w2;
                }
            }
        }
    }
    int orow = row0 + r;
    if (orow < 29){
#pragma unroll
        for (int i = 0; i < 4; i++){
            int oc = ocbase + cz * 4 + i;
            float sc = g_scale_s[oc], bi = g_bias_s[oc];
            float* op = g_s + (((size_t)b * C + oc) * 29 + orow) * 29;
#pragma unroll
            for (int j = 0; j < 8; j++){
                int ocol = c * 8 + j;
                if (ocol < 29){
                    float v = fmaf(sc, acc[i][j], bi);
                    op[ocol] = v > 0.f ? v : 0.f;
                }
            }
        }
    }
}

// ---------------- per-sample depthwise cross-correlation ----------------
// block: (b, 4-channel group). template + search channel staged in smem.
template<int TS, int PAD, int OS>
__global__ void __launch_bounds__(256) corr_kernel(const float* __restrict__ t,
                                                   float* __restrict__ out){
    __shared__ float s_s[4 * 841];
    __shared__ float s_t[4 * TS * TS];
    int tid = threadIdx.x;
    int cl = tid >> 6;          // channel within group (uniform per warp)
    int ps = tid & 63;
    int b = blockIdx.x;
    int c0 = blockIdx.y * 4;

    const float* sb = g_s + ((size_t)b * C + c0) * 841;
#pragma unroll 1
    for (int idx = tid; idx < 4 * 841; idx += 256) s_s[idx] = sb[idx];
    const float* tb = t + ((size_t)b * C + c0) * TS * TS;
#pragma unroll 1
    for (int idx = tid; idx < 4 * TS * TS; idx += 256) s_t[idx] = tb[idx];
    __syncthreads();

    const float* scn = s_s + cl * 841;
    const float* tcn = s_t + cl * TS * TS;
    for (int p = ps; p < OS * OS; p += 64){
        int py = p / OS, px = p % OS;
        float acc = 0.f;
#pragma unroll
        for (int i = 0; i < TS; i++){
            int sy = py + i - PAD;
            if ((unsigned)sy < 29u){
#pragma unroll
                for (int j = 0; j < TS; j++){
                    int sx = px + j - PAD;
                    if ((unsigned)sx < 29u)
                        acc += tcn[i * TS + j] * scn[sy * 29 + sx];
                }
            }
        }
        out[(((size_t)b * C + c0 + cl) * OS + py) * OS + px] = acc;
    }
}

// ---------------- fused head: 1x1 conv(256->256)+BN+ReLU -> 1x1 conv(256->1)+sigmoid --
// block: (16-pixel tile, b). thread = output channel n; k-chunked smem GEMV; cross-n reduce.
__global__ void __launch_bounds__(256) head_kernel(const float* __restrict__ x, int HW,
                                                   const float* __restrict__ w1,
                                                   const float* __restrict__ w2,
                                                   const float* __restrict__ b2,
                                                   float* __restrict__ out){
    __shared__ float s_w[32 * 257];   // w1 transposed chunk [kk][n], pad 257
    __shared__ float s_x[32 * 16];    // x chunk [kk][p]
    __shared__ float s_red[8][16];
    int tid = threadIdx.x;            // n = out channel of layer 1
    int b = blockIdx.y;
    int p0 = blockIdx.x * 16;
    const float* xb = x + (size_t)b * C * HW;

    float acc[16];
#pragma unroll
    for (int p = 0; p < 16; p++) acc[p] = 0.f;

    for (int k0 = 0; k0 < C; k0 += 32){
        __syncthreads();
#pragma unroll 1
        for (int idx = tid; idx < 256 * 32; idx += 256){
            int kk = idx & 31;
            int n  = idx >> 5;
            s_w[kk * 257 + n] = w1[n * C + k0 + kk];
        }
#pragma unroll 1
        for (int idx = tid; idx < 32 * 16; idx += 256){
            int p  = idx & 15;
            int kk = idx >> 4;
            int gp = p0 + p;
            s_x[kk * 16 + p] = (gp < HW) ? xb[(k0 + kk) * HW + gp] : 0.f;
        }
        __syncthreads();
#pragma unroll
        for (int kk = 0; kk < 32; kk++){
            float wv = s_w[kk * 257 + tid];
            const float4* xv = (const float4*)(s_x + kk * 16);
            float4 a0 = xv[0], a1 = xv[1], a2 = xv[2], a3 = xv[3];
            acc[0]  += wv * a0.x; acc[1]  += wv * a0.y; acc[2]  += wv * a0.z; acc[3]  += wv * a0.w;
            acc[4]  += wv * a1.x; acc[5]  += wv * a1.y; acc[6]  += wv * a1.z; acc[7]  += wv * a1.w;
            acc[8]  += wv * a2.x; acc[9]  += wv * a2.y; acc[10] += wv * a2.z; acc[11] += wv * a2.w;
            acc[12] += wv * a3.x; acc[13] += wv * a3.y; acc[14] += wv * a3.z; acc[15] += wv * a3.w;
        }
    }

    float sc = g_scale_1[tid], bi = g_bias_1[tid];
    float w2v = w2[tid];
    float contrib[16];
#pragma unroll
    for (int p = 0; p < 16; p++){
        float y = fmaf(sc, acc[p], bi);
        y = y > 0.f ? y : 0.f;
        contrib[p] = w2v * y;
    }
    int lane = tid & 31, wid = tid >> 5;
#pragma unroll
    for (int p = 0; p < 16; p++){
        float v = contrib[p];
        v += __shfl_xor_sync(0xffffffffu, v, 16);
        v += __shfl_xor_sync(0xffffffffu, v, 8);
        v += __shfl_xor_sync(0xffffffffu, v, 4);
        v += __shfl_xor_sync(0xffffffffu, v, 2);
        v += __shfl_xor_sync(0xffffffffu, v, 1);
        if (lane == 0) s_red[wid][p] = v;
    }
    __syncthreads();
    if (tid < 16){
        float v = 0.f;
#pragma unroll
        for (int wg = 0; wg < 8; wg++) v += s_red[wg][tid];
        int gp = p0 + tid;
        if (gp < HW){
            float z = v + b2[0];
            out[(size_t)b * HW + gp] = 1.f / (1.f + expf(-z));
        }
    }
}

// ---------------- launch ----------------
extern "C" void kernel_launch(void* const* d_in, const int* in_sizes, int n_in,
                              void* d_out, int out_size){
    const float* large  = (const float*)d_in[0];
    const float* medium = (const float*)d_in[1];
    const float* small  = (const float*)d_in[2];
    const float* search = (const float*)d_in[3];
    const float* wt  = (const float*)d_in[4];
    const float* bt  = (const float*)d_in[5];
    const float* gt  = (const float*)d_in[6];
    const float* bet = (const float*)d_in[7];
    const float* mt  = (const float*)d_in[8];
    const float* vt  = (const float*)d_in[9];
    const float* ws  = (const float*)d_in[10];
    const float* bs  = (const float*)d_in[11];
    const float* gs  = (const float*)d_in[12];
    const float* bes = (const float*)d_in[13];
    const float* ms  = (const float*)d_in[14];
    const float* vs  = (const float*)d_in[15];
    const float* w1  = (const float*)d_in[16];
    const float* b1  = (const float*)d_in[17];
    const float* g1  = (const float*)d_in[18];
    const float* be1 = (const float*)d_in[19];
    const float* m1  = (const float*)d_in[20];
    const float* v1  = (const float*)d_in[21];
    const float* w2  = (const float*)d_in[22];
    const float* b2  = (const float*)d_in[23];
    float* out = (float*)d_out;

    float *lf, *mf, *sf, *lc, *mc, *sc;
    cudaGetSymbolAddress((void**)&lf, g_lf);
    cudaGetSymbolAddress((void**)&mf, g_mf);
    cudaGetSymbolAddress((void**)&sf, g_sf);
    cudaGetSymbolAddress((void**)&lc, g_lc);
    cudaGetSymbolAddress((void**)&mc, g_mc);
    cudaGetSymbolAddress((void**)&sc, g_sc);

    prep_kernel<<<1, 256>>>(bt, gt, bet, mt, vt, bs, gs, bes, ms, vs, b1, g1, be1, m1, v1);

    conv_tmpl<9><<<dim3(64, 8), 256>>>(large,  wt, lf);
    conv_tmpl<7><<<dim3(64, 8), 256>>>(medium, wt, mf);
    conv_tmpl<5><<<dim3(64, 8), 256>>>(small,  wt, sf);
    conv_search<<<dim3(64, 16, 2), 256>>>(search, ws);

    corr_kernel<7, 2, 27><<<dim3(64, 64), 256>>>(lf, lc);
    corr_kernel<5, 0, 25><<<dim3(64, 64), 256>>>(mf, mc);
    corr_kernel<3, 0, 27><<<dim3(64, 64), 256>>>(sf, sc);

    head_kernel<<<dim3(46, 64), 256>>>(lc, 729, w1, w2, b2, out);
    head_kernel<<<dim3(40, 64), 256>>>(mc, 625, w1, w2, b2, out + 64 * 729);
    head_kernel<<<dim3(46, 64), 256>>>(sc, 729, w1, w2, b2, out + 64 * 729 + 64 * 625);
}